// round 2
// baseline (speedup 1.0000x reference)
#include <cuda_runtime.h>

#define EMBED    1024
#define HEADS    16
#define HEAD_DIM 64
#define BATCH    4
#define SEQ      2048
#define MTOT     (BATCH * SEQ)

// ---------------- scratch (no allocations allowed) ----------------
__device__ float g_Q[(size_t)BATCH * HEADS * SEQ * HEAD_DIM];
__device__ float g_K[(size_t)BATCH * HEADS * SEQ * HEAD_DIM];
__device__ float g_V[(size_t)BATCH * HEADS * SEQ * HEAD_DIM];
__device__ float g_ATT[(size_t)BATCH * SEQ * EMBED];

// ---------------- GEMM: C = A[M,K] @ W[N,K]^T + bias, optional scale ----
// MODE 0: C row-major [M, EMBED]
// MODE 1: scatter to [B, H, S, HEAD_DIM]  (m = b*SEQ+s, n = h*64+d)
#define BM 128
#define BN 128
#define BK 16
#define TM 8
#define TN 8

template <int MODE>
__global__ __launch_bounds__(256) void gemm_bias(
    const float* __restrict__ A, const float* __restrict__ W,
    const float* __restrict__ bias, float* __restrict__ C, float scale)
{
    __shared__ __align__(16) float As[BK][BM];
    __shared__ __align__(16) float Bs[BK][BN];

    const int tid = threadIdx.x;
    const int tx = tid & 15;        // 0..15  -> n
    const int ty = tid >> 4;        // 0..15  -> m
    const int bm = blockIdx.y * BM;
    const int bn = blockIdx.x * BN;
    const int K = EMBED;

    float acc[TM][TN];
#pragma unroll
    for (int i = 0; i < TM; i++)
#pragma unroll
        for (int j = 0; j < TN; j++) acc[i][j] = 0.f;

    for (int t = 0; t < K; t += BK) {
#pragma unroll
        for (int i = 0; i < 2; i++) {
            int idx = tid + i * 256;       // 0..511 float4 slots
            int row = idx >> 2;            // 0..127
            int kc  = (idx & 3) << 2;      // 0,4,8,12
            float4 va = *reinterpret_cast<const float4*>(
                &A[(size_t)(bm + row) * K + t + kc]);
            As[kc + 0][row] = va.x; As[kc + 1][row] = va.y;
            As[kc + 2][row] = va.z; As[kc + 3][row] = va.w;
            float4 vw = *reinterpret_cast<const float4*>(
                &W[(size_t)(bn + row) * K + t + kc]);
            Bs[kc + 0][row] = vw.x; Bs[kc + 1][row] = vw.y;
            Bs[kc + 2][row] = vw.z; Bs[kc + 3][row] = vw.w;
        }
        __syncthreads();

#pragma unroll
        for (int kk = 0; kk < BK; kk++) {
            float a[TM], b[TN];
#pragma unroll
            for (int i = 0; i < TM; i += 4) {
                float4 v = *reinterpret_cast<const float4*>(&As[kk][ty * TM + i]);
                a[i] = v.x; a[i + 1] = v.y; a[i + 2] = v.z; a[i + 3] = v.w;
            }
#pragma unroll
            for (int j = 0; j < TN; j += 4) {
                float4 v = *reinterpret_cast<const float4*>(&Bs[kk][tx * TN + j]);
                b[j] = v.x; b[j + 1] = v.y; b[j + 2] = v.z; b[j + 3] = v.w;
            }
#pragma unroll
            for (int i = 0; i < TM; i++)
#pragma unroll
                for (int j = 0; j < TN; j++)
                    acc[i][j] += a[i] * b[j];
        }
        __syncthreads();
    }

#pragma unroll
    for (int i = 0; i < TM; i++) {
        int m = bm + ty * TM + i;
#pragma unroll
        for (int j = 0; j < TN; j++) {
            int n = bn + tx * TN + j;
            float v = (acc[i][j] + bias[n]) * scale;
            if (MODE == 0) {
                C[(size_t)m * EMBED + n] = v;
            } else {
                int b_ = m >> 11;          // SEQ = 2048
                int s_ = m & (SEQ - 1);
                int h_ = n >> 6;           // HEAD_DIM = 64
                int d_ = n & 63;
                C[(((size_t)b_ * HEADS + h_) * SEQ + s_) * HEAD_DIM + d_] = v;
            }
        }
    }
}

// ---------------- causal flash attention, fp32 ----------------
// Q,K,V in [B,H,S,64] (Q pre-scaled by 1/8). Out written to [B,S,EMBED].
// 1 thread = 1 query row, 128 rows per CTA, key tiles of 32.
#define FM 128
#define FN 32

__global__ __launch_bounds__(128) void flash_attn(
    const float* __restrict__ Q, const float* __restrict__ K,
    const float* __restrict__ V, float* __restrict__ Out)
{
    __shared__ __align__(16) float Ks[FN][HEAD_DIM];
    __shared__ __align__(16) float Vs[FN][HEAD_DIM];

    const int tid = threadIdx.x;
    const int qb = blockIdx.x;
    const int bh = blockIdx.y;
    const int r = qb * FM + tid;

    const float* qptr = Q + ((size_t)bh * SEQ + r) * HEAD_DIM;
    float4 q4[16];
#pragma unroll
    for (int i = 0; i < 16; i++)
        q4[i] = reinterpret_cast<const float4*>(qptr)[i];

    float4 o4[16];
#pragma unroll
    for (int i = 0; i < 16; i++) o4[i] = make_float4(0.f, 0.f, 0.f, 0.f);

    float mrun = -1e30f, lrun = 0.f;

    const int nb = (qb + 1) * 4;     // key tiles covering [0, qb*128+128)
    const int nfull = qb * 4;        // tiles fully below the diagonal

    const float4* Kg = reinterpret_cast<const float4*>(K + (size_t)bh * SEQ * HEAD_DIM);
    const float4* Vg = reinterpret_cast<const float4*>(V + (size_t)bh * SEQ * HEAD_DIM);

    for (int kb = 0; kb < nb; kb++) {
        __syncthreads();
#pragma unroll
        for (int i = 0; i < 4; i++) {
            int idx = tid + i * 128;   // 0..511 float4 slots (32*64/4)
            reinterpret_cast<float4*>(&Ks[0][0])[idx] = Kg[kb * 512 + idx];
            reinterpret_cast<float4*>(&Vs[0][0])[idx] = Vg[kb * 512 + idx];
        }
        __syncthreads();

        float s[FN];
#pragma unroll
        for (int j = 0; j < FN; j++) {
            const float4* kr = reinterpret_cast<const float4*>(&Ks[j][0]);
            float s0 = 0.f, s1 = 0.f, s2 = 0.f, s3 = 0.f;
#pragma unroll
            for (int kk = 0; kk < 16; kk++) {
                float4 kv = kr[kk];
                s0 += q4[kk].x * kv.x;
                s1 += q4[kk].y * kv.y;
                s2 += q4[kk].z * kv.z;
                s3 += q4[kk].w * kv.w;
            }
            s[j] = (s0 + s1) + (s2 + s3);
        }

        if (kb >= nfull) {               // diagonal tile: per-element causal mask
            int ks = kb * FN;
#pragma unroll
            for (int j = 0; j < FN; j++)
                if (ks + j > r) s[j] = -1e30f;
        }

        float mx = mrun;
#pragma unroll
        for (int j = 0; j < FN; j++) mx = fmaxf(mx, s[j]);
        float alpha = __expf(mrun - mx);
        mrun = mx;

        float ls = 0.f;
#pragma unroll
        for (int j = 0; j < FN; j++) {
            float p = __expf(s[j] - mx);
            s[j] = p;
            ls += p;
        }
        lrun = lrun * alpha + ls;

#pragma unroll
        for (int i = 0; i < 16; i++) {
            o4[i].x *= alpha; o4[i].y *= alpha;
            o4[i].z *= alpha; o4[i].w *= alpha;
        }
#pragma unroll
        for (int j = 0; j < FN; j++) {
            float p = s[j];
            const float4* vr = reinterpret_cast<const float4*>(&Vs[j][0]);
#pragma unroll
            for (int i = 0; i < 16; i++) {
                float4 vv = vr[i];
                o4[i].x += p * vv.x; o4[i].y += p * vv.y;
                o4[i].z += p * vv.z; o4[i].w += p * vv.w;
            }
        }
    }

    float inv = 1.f / lrun;
    int b_ = bh / HEADS, h_ = bh % HEADS;
    float* op = Out + ((size_t)b_ * SEQ + r) * EMBED + h_ * HEAD_DIM;
#pragma unroll
    for (int i = 0; i < 16; i++) {
        float4 v = o4[i];
        v.x *= inv; v.y *= inv; v.z *= inv; v.w *= inv;
        reinterpret_cast<float4*>(op)[i] = v;
    }
}

// ---------------- launch ----------------
extern "C" void kernel_launch(void* const* d_in, const int* in_sizes, int n_in,
                              void* d_out, int out_size)
{
    const float* query  = (const float*)d_in[0];
    const float* key_in = (const float*)d_in[1];
    const float* value  = (const float*)d_in[2];
    // d_in[3] = mask (int32 tril) — causal applied analytically
    const float* Wq = (const float*)d_in[4];
    const float* bq = (const float*)d_in[5];
    const float* Wk = (const float*)d_in[6];
    const float* bk = (const float*)d_in[7];
    const float* Wv = (const float*)d_in[8];
    const float* bv = (const float*)d_in[9];
    const float* Wo = (const float*)d_in[10];
    const float* bo = (const float*)d_in[11];
    float* out = (float*)d_out;

    float *gq, *gk, *gv, *ga;
    cudaGetSymbolAddress((void**)&gq, g_Q);
    cudaGetSymbolAddress((void**)&gk, g_K);
    cudaGetSymbolAddress((void**)&gv, g_V);
    cudaGetSymbolAddress((void**)&ga, g_ATT);

    dim3 gp(EMBED / BN, MTOT / BM);   // (8, 64)
    // Q projection with 1/sqrt(Dh) folded in
    gemm_bias<1><<<gp, 256>>>(query,  Wq, bq, gq, 0.125f);
    gemm_bias<1><<<gp, 256>>>(key_in, Wk, bk, gk, 1.0f);
    gemm_bias<1><<<gp, 256>>>(value,  Wv, bv, gv, 1.0f);

    flash_attn<<<dim3(SEQ / FM, BATCH * HEADS), 128>>>(gq, gk, gv, ga);

    gemm_bias<0><<<gp, 256>>>(ga, Wo, bo, out, 1.0f);
}

// round 3
// speedup vs baseline: 2.0702x; 2.0702x over previous
#include <cuda_runtime.h>
#include <cstdint>

#define EMBED    1024
#define HEADS    16
#define HEAD_DIM 64
#define BATCH    4
#define SEQ      2048
#define MTOT     (BATCH * SEQ)

// ---------------- scratch (no allocations allowed) ----------------
__device__ float g_Q[(size_t)BATCH * HEADS * SEQ * HEAD_DIM];
__device__ float g_K[(size_t)BATCH * HEADS * SEQ * HEAD_DIM];
__device__ float g_V[(size_t)BATCH * HEADS * SEQ * HEAD_DIM];
__device__ float g_ATT[(size_t)BATCH * SEQ * EMBED];

// ============================================================
// tf32 tensor-core GEMM: C = A[M,K] @ W[N,K]^T + bias (opt scale)
// MODE 0: C row-major [M, EMBED]
// MODE 1: scatter to [B, H, S, HEAD_DIM]
// CTA tile 128x128x16, 8 warps (4M x 2N), warp tile 32x64
// smem layout [row][k] with stride 20 floats -> conflict-free frag LDS
// ============================================================
#define GBM 128
#define GBN 128
#define GBK 16
#define GSTR 20          // GBK + 4 pad
#define KITERS (EMBED / GBK)

__device__ __forceinline__ uint32_t f2tf32(float f) {
    uint32_t r;
    asm("cvt.rna.tf32.f32 %0, %1;" : "=r"(r) : "f"(f));
    return r;
}

__device__ __forceinline__ void mma_tf32(
    float& c0, float& c1, float& c2, float& c3,
    uint32_t a0, uint32_t a1, uint32_t a2, uint32_t a3,
    uint32_t b0, uint32_t b1)
{
    asm volatile(
        "mma.sync.aligned.m16n8k8.row.col.f32.tf32.tf32.f32 "
        "{%0,%1,%2,%3}, {%4,%5,%6,%7}, {%8,%9}, {%0,%1,%2,%3};\n"
        : "+f"(c0), "+f"(c1), "+f"(c2), "+f"(c3)
        : "r"(a0), "r"(a1), "r"(a2), "r"(a3), "r"(b0), "r"(b1));
}

template <int MODE>
__global__ __launch_bounds__(256, 2) void gemm_tc(
    const float* __restrict__ A, const float* __restrict__ W,
    const float* __restrict__ bias, float* __restrict__ C, float scale)
{
    __shared__ __align__(16) uint32_t As[GBM * GSTR];
    __shared__ __align__(16) uint32_t Bs[GBN * GSTR];

    const int tid  = threadIdx.x;
    const int lane = tid & 31;
    const int warp = tid >> 5;
    const int wm   = warp >> 1;          // 0..3
    const int wn   = warp & 1;           // 0..1
    const int g    = lane >> 2;          // groupID 0..7
    const int tg   = lane & 3;           // tid-in-group 0..3

    const int bm = blockIdx.y * GBM;
    const int bn = blockIdx.x * GBN;

    // gmem tile load mapping: 512 float4 slots per operand per BK tile
    const int r0 = tid >> 2;              // 0..63   (slot idx = tid)
    const int r1 = (tid + 256) >> 2;      // 64..127 (slot idx = tid+256)
    const int kc = (tid & 3) << 2;        // 0,4,8,12

    float acc[2][8][4];
#pragma unroll
    for (int i = 0; i < 2; i++)
#pragma unroll
        for (int j = 0; j < 8; j++)
#pragma unroll
            for (int v = 0; v < 4; v++) acc[i][j][v] = 0.f;

    const float4* A4 = reinterpret_cast<const float4*>(A);
    const float4* W4 = reinterpret_cast<const float4*>(W);
    // row stride in float4 units = EMBED/4 = 256
    float4 ra0 = A4[(size_t)(bm + r0) * 256 + (kc >> 2)];
    float4 ra1 = A4[(size_t)(bm + r1) * 256 + (kc >> 2)];
    float4 rb0 = W4[(size_t)(bn + r0) * 256 + (kc >> 2)];
    float4 rb1 = W4[(size_t)(bn + r1) * 256 + (kc >> 2)];

    for (int t = 0; t < KITERS; t++) {
        // store (with tf32 convert)
        {
            uint4 u;
            u.x = f2tf32(ra0.x); u.y = f2tf32(ra0.y); u.z = f2tf32(ra0.z); u.w = f2tf32(ra0.w);
            *reinterpret_cast<uint4*>(&As[r0 * GSTR + kc]) = u;
            u.x = f2tf32(ra1.x); u.y = f2tf32(ra1.y); u.z = f2tf32(ra1.z); u.w = f2tf32(ra1.w);
            *reinterpret_cast<uint4*>(&As[r1 * GSTR + kc]) = u;
            u.x = f2tf32(rb0.x); u.y = f2tf32(rb0.y); u.z = f2tf32(rb0.z); u.w = f2tf32(rb0.w);
            *reinterpret_cast<uint4*>(&Bs[r0 * GSTR + kc]) = u;
            u.x = f2tf32(rb1.x); u.y = f2tf32(rb1.y); u.z = f2tf32(rb1.z); u.w = f2tf32(rb1.w);
            *reinterpret_cast<uint4*>(&Bs[r1 * GSTR + kc]) = u;
        }
        __syncthreads();

        // prefetch next gmem tile
        if (t + 1 < KITERS) {
            int kf = (t + 1) * (GBK / 4) + (kc >> 2);
            ra0 = A4[(size_t)(bm + r0) * 256 + kf];
            ra1 = A4[(size_t)(bm + r1) * 256 + kf];
            rb0 = W4[(size_t)(bn + r0) * 256 + kf];
            rb1 = W4[(size_t)(bn + r1) * 256 + kf];
        }

#pragma unroll
        for (int ks = 0; ks < 2; ks++) {
            const int kb = ks * 8;
            // A fragments: rows wm*32 + mt*16 + {g, g+8}, cols kb + {tg, tg+4}
            uint32_t af[2][4];
#pragma unroll
            for (int mt = 0; mt < 2; mt++) {
                int mrow = wm * 32 + mt * 16 + g;
                af[mt][0] = As[mrow * GSTR + kb + tg];
                af[mt][1] = As[(mrow + 8) * GSTR + kb + tg];
                af[mt][2] = As[mrow * GSTR + kb + tg + 4];
                af[mt][3] = As[(mrow + 8) * GSTR + kb + tg + 4];
            }
            // B fragments + mma
#pragma unroll
            for (int nt = 0; nt < 8; nt++) {
                int nrow = wn * 64 + nt * 8 + g;
                uint32_t b0 = Bs[nrow * GSTR + kb + tg];
                uint32_t b1 = Bs[nrow * GSTR + kb + tg + 4];
#pragma unroll
                for (int mt = 0; mt < 2; mt++) {
                    mma_tf32(acc[mt][nt][0], acc[mt][nt][1],
                             acc[mt][nt][2], acc[mt][nt][3],
                             af[mt][0], af[mt][1], af[mt][2], af[mt][3],
                             b0, b1);
                }
            }
        }
        __syncthreads();
    }

    // epilogue
#pragma unroll
    for (int mt = 0; mt < 2; mt++) {
#pragma unroll
        for (int nt = 0; nt < 8; nt++) {
            int n = bn + wn * 64 + nt * 8 + tg * 2;
            float bia0 = bias[n], bia1 = bias[n + 1];
#pragma unroll
            for (int half = 0; half < 2; half++) {
                int m = bm + wm * 32 + mt * 16 + g + half * 8;
                float v0 = (acc[mt][nt][half * 2 + 0] + bia0) * scale;
                float v1 = (acc[mt][nt][half * 2 + 1] + bia1) * scale;
                if (MODE == 0) {
                    *reinterpret_cast<float2*>(&C[(size_t)m * EMBED + n]) =
                        make_float2(v0, v1);
                } else {
                    int b_ = m >> 11;
                    int s_ = m & (SEQ - 1);
                    int h_ = n >> 6;
                    int d_ = n & 63;
                    *reinterpret_cast<float2*>(
                        &C[(((size_t)b_ * HEADS + h_) * SEQ + s_) * HEAD_DIM + d_]) =
                        make_float2(v0, v1);
                }
            }
        }
    }
}

// ============================================================
// causal flash attention, fp32, 2 threads per query row
// Q,K,V in [B,H,S,64] (Q pre-scaled). Out -> [B,S,EMBED]
// 256 threads, 128 rows/CTA, key tiles of 32
// ============================================================
#define FM 128
#define FN 32

__global__ __launch_bounds__(256, 2) void flash_attn(
    const float* __restrict__ Q, const float* __restrict__ K,
    const float* __restrict__ V, float* __restrict__ Out)
{
    __shared__ __align__(16) float Ks[FN][HEAD_DIM];
    __shared__ __align__(16) float Vs[FN][HEAD_DIM];

    const int tid  = threadIdx.x;
    const int row  = tid >> 1;            // 0..127
    const int half = tid & 1;             // 0 or 1 (owns 32 of Dh)
    const int qb = blockIdx.x;
    const int bh = blockIdx.y;
    const int r = qb * FM + row;

    const float* qptr = Q + ((size_t)bh * SEQ + r) * HEAD_DIM + half * 32;
    float4 q4[8];
#pragma unroll
    for (int i = 0; i < 8; i++)
        q4[i] = reinterpret_cast<const float4*>(qptr)[i];

    float4 o4[8];
#pragma unroll
    for (int i = 0; i < 8; i++) o4[i] = make_float4(0.f, 0.f, 0.f, 0.f);

    float mrun = -1e30f, lrun = 0.f;

    const int nb = (qb + 1) * 4;
    const int nfull = qb * 4;

    const float4* Kg = reinterpret_cast<const float4*>(K + (size_t)bh * SEQ * HEAD_DIM);
    const float4* Vg = reinterpret_cast<const float4*>(V + (size_t)bh * SEQ * HEAD_DIM);

    for (int kb = 0; kb < nb; kb++) {
        __syncthreads();
#pragma unroll
        for (int i = 0; i < 2; i++) {
            int idx = tid + i * 256;   // 512 float4 slots (32*64/4)
            reinterpret_cast<float4*>(&Ks[0][0])[idx] = Kg[kb * 512 + idx];
            reinterpret_cast<float4*>(&Vs[0][0])[idx] = Vg[kb * 512 + idx];
        }
        __syncthreads();

        float s[FN];
#pragma unroll
        for (int j = 0; j < FN; j++) {
            const float4* kr = reinterpret_cast<const float4*>(&Ks[j][half * 32]);
            float s0 = 0.f, s1 = 0.f, s2 = 0.f, s3 = 0.f;
#pragma unroll
            for (int kk = 0; kk < 8; kk++) {
                float4 kv = kr[kk];
                s0 += q4[kk].x * kv.x;
                s1 += q4[kk].y * kv.y;
                s2 += q4[kk].z * kv.z;
                s3 += q4[kk].w * kv.w;
            }
            float part = (s0 + s1) + (s2 + s3);
            s[j] = part + __shfl_xor_sync(0xffffffffu, part, 1);
        }

        if (kb >= nfull) {               // diagonal tile: per-element mask
            int ks0 = kb * FN;
#pragma unroll
            for (int j = 0; j < FN; j++)
                if (ks0 + j > r) s[j] = -1e30f;
        }

        float mx = mrun;
#pragma unroll
        for (int j = 0; j < FN; j++) mx = fmaxf(mx, s[j]);
        float alpha = __expf(mrun - mx);
        mrun = mx;

        float ls = 0.f;
#pragma unroll
        for (int j = 0; j < FN; j++) {
            float p = __expf(s[j] - mx);
            s[j] = p;
            ls += p;
        }
        lrun = lrun * alpha + ls;

#pragma unroll
        for (int i = 0; i < 8; i++) {
            o4[i].x *= alpha; o4[i].y *= alpha;
            o4[i].z *= alpha; o4[i].w *= alpha;
        }
#pragma unroll
        for (int j = 0; j < FN; j++) {
            float p = s[j];
            const float4* vr = reinterpret_cast<const float4*>(&Vs[j][half * 32]);
#pragma unroll
            for (int i = 0; i < 8; i++) {
                float4 vv = vr[i];
                o4[i].x += p * vv.x; o4[i].y += p * vv.y;
                o4[i].z += p * vv.z; o4[i].w += p * vv.w;
            }
        }
    }

    float inv = 1.f / lrun;
    int b_ = bh / HEADS, h_ = bh % HEADS;
    float* op = Out + ((size_t)b_ * SEQ + r) * EMBED + h_ * HEAD_DIM + half * 32;
#pragma unroll
    for (int i = 0; i < 8; i++) {
        float4 v = o4[i];
        v.x *= inv; v.y *= inv; v.z *= inv; v.w *= inv;
        reinterpret_cast<float4*>(op)[i] = v;
    }
}

// ---------------- launch ----------------
extern "C" void kernel_launch(void* const* d_in, const int* in_sizes, int n_in,
                              void* d_out, int out_size)
{
    const float* query  = (const float*)d_in[0];
    const float* key_in = (const float*)d_in[1];
    const float* value  = (const float*)d_in[2];
    // d_in[3] = mask (int32 tril) — causal applied analytically
    const float* Wq = (const float*)d_in[4];
    const float* bq = (const float*)d_in[5];
    const float* Wk = (const float*)d_in[6];
    const float* bk = (const float*)d_in[7];
    const float* Wv = (const float*)d_in[8];
    const float* bv = (const float*)d_in[9];
    const float* Wo = (const float*)d_in[10];
    const float* bo = (const float*)d_in[11];
    float* out = (float*)d_out;

    float *gq, *gk, *gv, *ga;
    cudaGetSymbolAddress((void**)&gq, g_Q);
    cudaGetSymbolAddress((void**)&gk, g_K);
    cudaGetSymbolAddress((void**)&gv, g_V);
    cudaGetSymbolAddress((void**)&ga, g_ATT);

    dim3 gp(EMBED / GBN, MTOT / GBM);   // (8, 64)
    gemm_tc<1><<<gp, 256>>>(query,  Wq, bq, gq, 0.125f);   // 1/sqrt(64) folded
    gemm_tc<1><<<gp, 256>>>(key_in, Wk, bk, gk, 1.0f);
    gemm_tc<1><<<gp, 256>>>(value,  Wv, bv, gv, 1.0f);

    flash_attn<<<dim3(SEQ / FM, BATCH * HEADS), 256>>>(gq, gk, gv, ga);

    gemm_tc<0><<<gp, 256>>>(ga, Wo, bo, out, 1.0f);
}

// round 4
// speedup vs baseline: 6.4087x; 3.0956x over previous
#include <cuda_runtime.h>
#include <cstdint>

#define EMBED    1024
#define HEADS    16
#define HEAD_DIM 64
#define BATCH    4
#define SEQ      2048
#define MTOT     (BATCH * SEQ)

// ---------------- scratch (no allocations allowed) ----------------
__device__ float g_Q[(size_t)BATCH * HEADS * SEQ * HEAD_DIM];
__device__ float g_K[(size_t)BATCH * HEADS * SEQ * HEAD_DIM];
__device__ float g_V[(size_t)BATCH * HEADS * SEQ * HEAD_DIM];
__device__ float g_ATT[(size_t)BATCH * SEQ * EMBED];

__device__ __forceinline__ uint32_t f2tf32(float f) {
    uint32_t r;
    asm("cvt.rna.tf32.f32 %0, %1;" : "=r"(r) : "f"(f));
    return r;
}

__device__ __forceinline__ float exp2a(float x) {
    float r;
    asm("ex2.approx.f32 %0, %1;" : "=f"(r) : "f"(x));
    return r;
}

__device__ __forceinline__ void mma_tf32(
    float& c0, float& c1, float& c2, float& c3,
    uint32_t a0, uint32_t a1, uint32_t a2, uint32_t a3,
    uint32_t b0, uint32_t b1)
{
    asm volatile(
        "mma.sync.aligned.m16n8k8.row.col.f32.tf32.tf32.f32 "
        "{%0,%1,%2,%3}, {%4,%5,%6,%7}, {%8,%9}, {%0,%1,%2,%3};\n"
        : "+f"(c0), "+f"(c1), "+f"(c2), "+f"(c3)
        : "r"(a0), "r"(a1), "r"(a2), "r"(a3), "r"(b0), "r"(b1));
}

// ============================================================
// tf32 tensor-core GEMM: C = A[M,K] @ W[N,K]^T + bias (opt scale)
// ============================================================
#define GBM 128
#define GBN 128
#define GBK 16
#define GSTR 20
#define KITERS (EMBED / GBK)

template <int MODE>
__global__ __launch_bounds__(256, 2) void gemm_tc(
    const float* __restrict__ A, const float* __restrict__ W,
    const float* __restrict__ bias, float* __restrict__ C, float scale)
{
    __shared__ __align__(16) uint32_t As[GBM * GSTR];
    __shared__ __align__(16) uint32_t Bs[GBN * GSTR];

    const int tid  = threadIdx.x;
    const int lane = tid & 31;
    const int warp = tid >> 5;
    const int wm   = warp >> 1;
    const int wn   = warp & 1;
    const int g    = lane >> 2;
    const int tg   = lane & 3;

    const int bm = blockIdx.y * GBM;
    const int bn = blockIdx.x * GBN;

    const int r0 = tid >> 2;
    const int r1 = (tid + 256) >> 2;
    const int kc = (tid & 3) << 2;

    float acc[2][8][4];
#pragma unroll
    for (int i = 0; i < 2; i++)
#pragma unroll
        for (int j = 0; j < 8; j++)
#pragma unroll
            for (int v = 0; v < 4; v++) acc[i][j][v] = 0.f;

    const float4* A4 = reinterpret_cast<const float4*>(A);
    const float4* W4 = reinterpret_cast<const float4*>(W);
    float4 ra0 = A4[(size_t)(bm + r0) * 256 + (kc >> 2)];
    float4 ra1 = A4[(size_t)(bm + r1) * 256 + (kc >> 2)];
    float4 rb0 = W4[(size_t)(bn + r0) * 256 + (kc >> 2)];
    float4 rb1 = W4[(size_t)(bn + r1) * 256 + (kc >> 2)];

    for (int t = 0; t < KITERS; t++) {
        {
            uint4 u;
            u.x = f2tf32(ra0.x); u.y = f2tf32(ra0.y); u.z = f2tf32(ra0.z); u.w = f2tf32(ra0.w);
            *reinterpret_cast<uint4*>(&As[r0 * GSTR + kc]) = u;
            u.x = f2tf32(ra1.x); u.y = f2tf32(ra1.y); u.z = f2tf32(ra1.z); u.w = f2tf32(ra1.w);
            *reinterpret_cast<uint4*>(&As[r1 * GSTR + kc]) = u;
            u.x = f2tf32(rb0.x); u.y = f2tf32(rb0.y); u.z = f2tf32(rb0.z); u.w = f2tf32(rb0.w);
            *reinterpret_cast<uint4*>(&Bs[r0 * GSTR + kc]) = u;
            u.x = f2tf32(rb1.x); u.y = f2tf32(rb1.y); u.z = f2tf32(rb1.z); u.w = f2tf32(rb1.w);
            *reinterpret_cast<uint4*>(&Bs[r1 * GSTR + kc]) = u;
        }
        __syncthreads();

        if (t + 1 < KITERS) {
            int kf = (t + 1) * (GBK / 4) + (kc >> 2);
            ra0 = A4[(size_t)(bm + r0) * 256 + kf];
            ra1 = A4[(size_t)(bm + r1) * 256 + kf];
            rb0 = W4[(size_t)(bn + r0) * 256 + kf];
            rb1 = W4[(size_t)(bn + r1) * 256 + kf];
        }

#pragma unroll
        for (int ks = 0; ks < 2; ks++) {
            const int kb = ks * 8;
            uint32_t af[2][4];
#pragma unroll
            for (int mt = 0; mt < 2; mt++) {
                int mrow = wm * 32 + mt * 16 + g;
                af[mt][0] = As[mrow * GSTR + kb + tg];
                af[mt][1] = As[(mrow + 8) * GSTR + kb + tg];
                af[mt][2] = As[mrow * GSTR + kb + tg + 4];
                af[mt][3] = As[(mrow + 8) * GSTR + kb + tg + 4];
            }
#pragma unroll
            for (int nt = 0; nt < 8; nt++) {
                int nrow = wn * 64 + nt * 8 + g;
                uint32_t b0 = Bs[nrow * GSTR + kb + tg];
                uint32_t b1 = Bs[nrow * GSTR + kb + tg + 4];
#pragma unroll
                for (int mt = 0; mt < 2; mt++) {
                    mma_tf32(acc[mt][nt][0], acc[mt][nt][1],
                             acc[mt][nt][2], acc[mt][nt][3],
                             af[mt][0], af[mt][1], af[mt][2], af[mt][3],
                             b0, b1);
                }
            }
        }
        __syncthreads();
    }

#pragma unroll
    for (int mt = 0; mt < 2; mt++) {
#pragma unroll
        for (int nt = 0; nt < 8; nt++) {
            int n = bn + wn * 64 + nt * 8 + tg * 2;
            float bia0 = bias[n], bia1 = bias[n + 1];
#pragma unroll
            for (int half = 0; half < 2; half++) {
                int m = bm + wm * 32 + mt * 16 + g + half * 8;
                float v0 = (acc[mt][nt][half * 2 + 0] + bia0) * scale;
                float v1 = (acc[mt][nt][half * 2 + 1] + bia1) * scale;
                if (MODE == 0) {
                    *reinterpret_cast<float2*>(&C[(size_t)m * EMBED + n]) =
                        make_float2(v0, v1);
                } else {
                    int b_ = m >> 11;
                    int s_ = m & (SEQ - 1);
                    int h_ = n >> 6;
                    int d_ = n & 63;
                    *reinterpret_cast<float2*>(
                        &C[(((size_t)b_ * HEADS + h_) * SEQ + s_) * HEAD_DIM + d_]) =
                        make_float2(v0, v1);
                }
            }
        }
    }
}

// ============================================================
// tensor-core causal flash attention (tf32 mma, fp32 accum)
// Q pre-scaled by 0.125*log2(e); softmax in exp2 domain.
// CTA: 128 rows, 8 warps x 16 rows; key tile 64.
// Ks [64][68], Vs [64][72] (row j, col d), Ps per-warp [16][68].
// ============================================================
#define KS_STR 68
#define VS_STR 72
#define PS_STR 68
#define FTC_SMEM_FLOATS (64 * KS_STR + 64 * VS_STR + 128 * PS_STR)
#define FTC_SMEM_BYTES  (FTC_SMEM_FLOATS * 4)

__global__ __launch_bounds__(256, 2) void flash_tc(
    const float* __restrict__ Q, const float* __restrict__ K,
    const float* __restrict__ V, float* __restrict__ Out)
{
    extern __shared__ uint32_t sm[];
    uint32_t* Ks = sm;                                // [64][68]
    uint32_t* Vs = sm + 64 * KS_STR;                  // [64][72]
    uint32_t* Ps = sm + 64 * KS_STR + 64 * VS_STR;    // [128][68]

    const int tid  = threadIdx.x;
    const int lane = tid & 31;
    const int w    = tid >> 5;
    const int g    = lane >> 2;
    const int tg   = lane & 3;

    const int qb = (int)gridDim.x - 1 - (int)blockIdx.x;  // big workloads first
    const int bh = blockIdx.y;
    const int wrow = qb * 128 + w * 16;

    // ---- Q fragments (held in registers for the whole kernel) ----
    const float* qbase = Q + ((size_t)bh * SEQ + wrow) * HEAD_DIM;
    uint32_t qf[8][4];
#pragma unroll
    for (int kk = 0; kk < 8; kk++) {
        qf[kk][0] = f2tf32(qbase[(size_t)g * 64 + kk * 8 + tg]);
        qf[kk][1] = f2tf32(qbase[(size_t)(g + 8) * 64 + kk * 8 + tg]);
        qf[kk][2] = f2tf32(qbase[(size_t)g * 64 + kk * 8 + tg + 4]);
        qf[kk][3] = f2tf32(qbase[(size_t)(g + 8) * 64 + kk * 8 + tg + 4]);
    }

    float oacc[8][4];
#pragma unroll
    for (int nt = 0; nt < 8; nt++)
#pragma unroll
        for (int c = 0; c < 4; c++) oacc[nt][c] = 0.f;

    float m0 = -1e30f, m1 = -1e30f, l0 = 0.f, l1 = 0.f;

    const float4* Kg = reinterpret_cast<const float4*>(K + (size_t)bh * SEQ * HEAD_DIM);
    const float4* Vg = reinterpret_cast<const float4*>(V + (size_t)bh * SEQ * HEAD_DIM);
    uint32_t* Pw = Ps + w * 16 * PS_STR;

    const int nbt = 2 * qb + 2;
    const int nfull = 2 * qb;

    for (int kb = 0; kb < nbt; kb++) {
        const int ks = kb * 64;
        __syncthreads();
#pragma unroll
        for (int i = 0; i < 4; i++) {
            int idx = tid + i * 256;
            int j = idx >> 4;
            int dq = idx & 15;
            float4 kv = Kg[(size_t)(ks + j) * 16 + dq];
            uint4 uk;
            uk.x = f2tf32(kv.x); uk.y = f2tf32(kv.y);
            uk.z = f2tf32(kv.z); uk.w = f2tf32(kv.w);
            *reinterpret_cast<uint4*>(&Ks[j * KS_STR + dq * 4]) = uk;
            float4 vv = Vg[(size_t)(ks + j) * 16 + dq];
            uint4 uv;
            uv.x = f2tf32(vv.x); uv.y = f2tf32(vv.y);
            uv.z = f2tf32(vv.z); uv.w = f2tf32(vv.w);
            *reinterpret_cast<uint4*>(&Vs[j * VS_STR + dq * 4]) = uv;
        }
        __syncthreads();

        if (ks <= wrow + 15) {   // warp has >=1 valid key in this tile
            // ---- S = Q K^T ----
            float sacc[8][4];
#pragma unroll
            for (int nt = 0; nt < 8; nt++)
#pragma unroll
                for (int c = 0; c < 4; c++) sacc[nt][c] = 0.f;

#pragma unroll
            for (int kk = 0; kk < 8; kk++) {
#pragma unroll
                for (int nt = 0; nt < 8; nt++) {
                    uint32_t b0 = Ks[(nt * 8 + g) * KS_STR + kk * 8 + tg];
                    uint32_t b1 = Ks[(nt * 8 + g) * KS_STR + kk * 8 + tg + 4];
                    mma_tf32(sacc[nt][0], sacc[nt][1], sacc[nt][2], sacc[nt][3],
                             qf[kk][0], qf[kk][1], qf[kk][2], qf[kk][3], b0, b1);
                }
            }

            if (kb >= nfull) {   // diagonal tile: elementwise causal mask
#pragma unroll
                for (int nt = 0; nt < 8; nt++) {
                    int col = ks + nt * 8 + 2 * tg;
                    if (col     > wrow + g)     sacc[nt][0] = -1e30f;
                    if (col + 1 > wrow + g)     sacc[nt][1] = -1e30f;
                    if (col     > wrow + g + 8) sacc[nt][2] = -1e30f;
                    if (col + 1 > wrow + g + 8) sacc[nt][3] = -1e30f;
                }
            }

            // ---- online softmax (exp2 domain) ----
            float rm0 = -1e30f, rm1 = -1e30f;
#pragma unroll
            for (int nt = 0; nt < 8; nt++) {
                rm0 = fmaxf(rm0, fmaxf(sacc[nt][0], sacc[nt][1]));
                rm1 = fmaxf(rm1, fmaxf(sacc[nt][2], sacc[nt][3]));
            }
            rm0 = fmaxf(rm0, __shfl_xor_sync(0xffffffffu, rm0, 1));
            rm0 = fmaxf(rm0, __shfl_xor_sync(0xffffffffu, rm0, 2));
            rm1 = fmaxf(rm1, __shfl_xor_sync(0xffffffffu, rm1, 1));
            rm1 = fmaxf(rm1, __shfl_xor_sync(0xffffffffu, rm1, 2));

            float mn0 = fmaxf(m0, rm0), mn1 = fmaxf(m1, rm1);
            float a0 = exp2a(m0 - mn0), a1 = exp2a(m1 - mn1);
            m0 = mn0; m1 = mn1;

            float ls0 = 0.f, ls1 = 0.f;
#pragma unroll
            for (int nt = 0; nt < 8; nt++) {
                float p0 = exp2a(sacc[nt][0] - mn0);
                float p1 = exp2a(sacc[nt][1] - mn0);
                float p2 = exp2a(sacc[nt][2] - mn1);
                float p3 = exp2a(sacc[nt][3] - mn1);
                sacc[nt][0] = p0; sacc[nt][1] = p1;
                sacc[nt][2] = p2; sacc[nt][3] = p3;
                ls0 += p0 + p1; ls1 += p2 + p3;
            }
            ls0 += __shfl_xor_sync(0xffffffffu, ls0, 1);
            ls0 += __shfl_xor_sync(0xffffffffu, ls0, 2);
            ls1 += __shfl_xor_sync(0xffffffffu, ls1, 1);
            ls1 += __shfl_xor_sync(0xffffffffu, ls1, 2);
            l0 = l0 * a0 + ls0;
            l1 = l1 * a1 + ls1;

            // rescale O
#pragma unroll
            for (int nt = 0; nt < 8; nt++) {
                oacc[nt][0] *= a0; oacc[nt][1] *= a0;
                oacc[nt][2] *= a1; oacc[nt][3] *= a1;
            }

            // ---- P -> per-warp smem (acc layout -> A-frag layout) ----
#pragma unroll
            for (int nt = 0; nt < 8; nt++) {
                uint2 u0;
                u0.x = f2tf32(sacc[nt][0]); u0.y = f2tf32(sacc[nt][1]);
                *reinterpret_cast<uint2*>(&Pw[g * PS_STR + nt * 8 + 2 * tg]) = u0;
                uint2 u1;
                u1.x = f2tf32(sacc[nt][2]); u1.y = f2tf32(sacc[nt][3]);
                *reinterpret_cast<uint2*>(&Pw[(g + 8) * PS_STR + nt * 8 + 2 * tg]) = u1;
            }
            __syncwarp();

            // ---- O += P V ----
#pragma unroll
            for (int kk = 0; kk < 8; kk++) {
                uint32_t pa0 = Pw[g * PS_STR + kk * 8 + tg];
                uint32_t pa1 = Pw[(g + 8) * PS_STR + kk * 8 + tg];
                uint32_t pa2 = Pw[g * PS_STR + kk * 8 + tg + 4];
                uint32_t pa3 = Pw[(g + 8) * PS_STR + kk * 8 + tg + 4];
#pragma unroll
                for (int nt = 0; nt < 8; nt++) {
                    uint32_t b0 = Vs[(kk * 8 + tg) * VS_STR + nt * 8 + g];
                    uint32_t b1 = Vs[(kk * 8 + tg + 4) * VS_STR + nt * 8 + g];
                    mma_tf32(oacc[nt][0], oacc[nt][1], oacc[nt][2], oacc[nt][3],
                             pa0, pa1, pa2, pa3, b0, b1);
                }
            }
        }
    }

    // ---- epilogue: divide by l, scatter to [B,S,EMBED] ----
    float inv0 = 1.f / l0, inv1 = 1.f / l1;
    int b_ = bh >> 4, h_ = bh & 15;
    int r0 = wrow + g, r1 = wrow + g + 8;
    float* o0 = Out + ((size_t)b_ * SEQ + r0) * EMBED + h_ * 64;
    float* o1 = Out + ((size_t)b_ * SEQ + r1) * EMBED + h_ * 64;
#pragma unroll
    for (int nt = 0; nt < 8; nt++) {
        *reinterpret_cast<float2*>(&o0[nt * 8 + 2 * tg]) =
            make_float2(oacc[nt][0] * inv0, oacc[nt][1] * inv0);
        *reinterpret_cast<float2*>(&o1[nt * 8 + 2 * tg]) =
            make_float2(oacc[nt][2] * inv1, oacc[nt][3] * inv1);
    }
}

// ---------------- launch ----------------
extern "C" void kernel_launch(void* const* d_in, const int* in_sizes, int n_in,
                              void* d_out, int out_size)
{
    const float* query  = (const float*)d_in[0];
    const float* key_in = (const float*)d_in[1];
    const float* value  = (const float*)d_in[2];
    // d_in[3] = mask (int32 tril) — causal applied analytically
    const float* Wq = (const float*)d_in[4];
    const float* bq = (const float*)d_in[5];
    const float* Wk = (const float*)d_in[6];
    const float* bk = (const float*)d_in[7];
    const float* Wv = (const float*)d_in[8];
    const float* bv = (const float*)d_in[9];
    const float* Wo = (const float*)d_in[10];
    const float* bo = (const float*)d_in[11];
    float* out = (float*)d_out;

    float *gq, *gk, *gv, *ga;
    cudaGetSymbolAddress((void**)&gq, g_Q);
    cudaGetSymbolAddress((void**)&gk, g_K);
    cudaGetSymbolAddress((void**)&gv, g_V);
    cudaGetSymbolAddress((void**)&ga, g_ATT);

    cudaFuncSetAttribute(flash_tc,
                         cudaFuncAttributeMaxDynamicSharedMemorySize,
                         FTC_SMEM_BYTES);

    dim3 gp(EMBED / GBN, MTOT / GBM);   // (8, 64)
    // Q scaled by 1/sqrt(64) * log2(e) so softmax uses ex2 directly
    gemm_tc<1><<<gp, 256>>>(query,  Wq, bq, gq, 0.18033688011112042f);
    gemm_tc<1><<<gp, 256>>>(key_in, Wk, bk, gk, 1.0f);
    gemm_tc<1><<<gp, 256>>>(value,  Wv, bv, gv, 1.0f);

    flash_tc<<<dim3(SEQ / 128, BATCH * HEADS), 256, FTC_SMEM_BYTES>>>(gq, gk, gv, ga);

    gemm_tc<0><<<gp, 256>>>(ga, Wo, bo, out, 1.0f);
}

// round 7
// speedup vs baseline: 10.7624x; 1.6793x over previous
#include <cuda_runtime.h>
#include <cuda_fp16.h>
#include <cstdint>

#define EMBED    1024
#define HEADS    16
#define HEAD_DIM 64
#define BATCH    4
#define SEQ      2048
#define MTOT     (BATCH * SEQ)

// ---------------- scratch (no allocations allowed) ----------------
__device__ float g_Q[(size_t)BATCH * HEADS * SEQ * HEAD_DIM];
__device__ float g_K[(size_t)BATCH * HEADS * SEQ * HEAD_DIM];
__device__ float g_V[(size_t)BATCH * HEADS * SEQ * HEAD_DIM];
__device__ float g_ATT[(size_t)BATCH * SEQ * EMBED];

// ---------------- helpers ----------------
__device__ __forceinline__ uint32_t h2pack(float a, float b) {
    uint32_t r;
    asm("cvt.rn.f16x2.f32 %0, %1, %2;" : "=r"(r) : "f"(b), "f"(a));
    return r;
}

__device__ __forceinline__ float exp2a(float x) {
    float r;
    asm("ex2.approx.f32 %0, %1;" : "=f"(r) : "f"(x));
    return r;
}

__device__ __forceinline__ void mma_f16(
    float& c0, float& c1, float& c2, float& c3,
    uint32_t a0, uint32_t a1, uint32_t a2, uint32_t a3,
    uint32_t b0, uint32_t b1)
{
    asm volatile(
        "mma.sync.aligned.m16n8k16.row.col.f32.f16.f16.f32 "
        "{%0,%1,%2,%3}, {%4,%5,%6,%7}, {%8,%9}, {%0,%1,%2,%3};\n"
        : "+f"(c0), "+f"(c1), "+f"(c2), "+f"(c3)
        : "r"(a0), "r"(a1), "r"(a2), "r"(a3), "r"(b0), "r"(b1));
}

// ============================================================
// fp16 tensor-core GEMM: C = A[M,1024] @ W[N,1024]^T + bias (x scale)
// CTA 128x128, BK=32 (2 x k16 mma steps), 8 warps (4M x 2N), warp 32x64.
// smem: half2 arrays [row][16 cols + pad], stride 20 uint32.
// MODE 0: row-major out [M,EMBED]. MODE 1: scatter [B,H,S,Dh].
// ============================================================
#define GBM 128
#define GBN 128
#define GBK 32
#define GSTR 20
#define KITERS (EMBED / GBK)   // 32

template <int MODE>
__global__ __launch_bounds__(256, 2) void gemm_f16(
    const float* __restrict__ A, const float* __restrict__ W,
    const float* __restrict__ bias, float* __restrict__ C, float scale)
{
    __shared__ __align__(16) uint32_t As2[GBM * GSTR];
    __shared__ __align__(16) uint32_t Bs2[GBN * GSTR];

    const int tid  = threadIdx.x;
    const int lane = tid & 31;
    const int warp = tid >> 5;
    const int wm   = warp >> 1;
    const int wn   = warp & 1;
    const int g    = lane >> 2;
    const int tg   = lane & 3;

    const int bm = blockIdx.y * GBM;
    const int bn = blockIdx.x * GBN;

    float acc[2][8][4];
#pragma unroll
    for (int i = 0; i < 2; i++)
#pragma unroll
        for (int j = 0; j < 8; j++)
#pragma unroll
            for (int v = 0; v < 4; v++) acc[i][j][v] = 0.f;

    const float4* A4 = reinterpret_cast<const float4*>(A);
    const float4* W4 = reinterpret_cast<const float4*>(W);

    // per-thread gmem mapping: 4 float4 per operand per BK tile
    int rowi[4], d4i[4];
#pragma unroll
    for (int i = 0; i < 4; i++) {
        int idx = tid + i * 256;
        rowi[i] = idx >> 3;        // 0..127
        d4i[i]  = idx & 7;         // 0..7 (8 float4 per 32-float row)
    }

    float4 ra[4], rb[4];
#pragma unroll
    for (int i = 0; i < 4; i++) {
        ra[i] = A4[(size_t)(bm + rowi[i]) * 256 + d4i[i]];
        rb[i] = W4[(size_t)(bn + rowi[i]) * 256 + d4i[i]];
    }

    for (int t = 0; t < KITERS; t++) {
        // store with fp16 conversion (2 half2 per float4)
#pragma unroll
        for (int i = 0; i < 4; i++) {
            uint2 ua = make_uint2(h2pack(ra[i].x, ra[i].y), h2pack(ra[i].z, ra[i].w));
            *reinterpret_cast<uint2*>(&As2[rowi[i] * GSTR + d4i[i] * 2]) = ua;
            uint2 ub = make_uint2(h2pack(rb[i].x, rb[i].y), h2pack(rb[i].z, rb[i].w));
            *reinterpret_cast<uint2*>(&Bs2[rowi[i] * GSTR + d4i[i] * 2]) = ub;
        }
        __syncthreads();

        if (t + 1 < KITERS) {
            int kf = (t + 1) * (GBK / 4);
#pragma unroll
            for (int i = 0; i < 4; i++) {
                ra[i] = A4[(size_t)(bm + rowi[i]) * 256 + kf + d4i[i]];
                rb[i] = W4[(size_t)(bn + rowi[i]) * 256 + kf + d4i[i]];
            }
        }

#pragma unroll
        for (int ks = 0; ks < 2; ks++) {
            const int cb = ks * 8;
            uint32_t af[2][4];
#pragma unroll
            for (int mt = 0; mt < 2; mt++) {
                int mrow = wm * 32 + mt * 16 + g;
                af[mt][0] = As2[mrow * GSTR + cb + tg];
                af[mt][1] = As2[(mrow + 8) * GSTR + cb + tg];
                af[mt][2] = As2[mrow * GSTR + cb + tg + 4];
                af[mt][3] = As2[(mrow + 8) * GSTR + cb + tg + 4];
            }
#pragma unroll
            for (int nt = 0; nt < 8; nt++) {
                int nrow = wn * 64 + nt * 8 + g;
                uint32_t b0 = Bs2[nrow * GSTR + cb + tg];
                uint32_t b1 = Bs2[nrow * GSTR + cb + tg + 4];
#pragma unroll
                for (int mt = 0; mt < 2; mt++) {
                    mma_f16(acc[mt][nt][0], acc[mt][nt][1],
                            acc[mt][nt][2], acc[mt][nt][3],
                            af[mt][0], af[mt][1], af[mt][2], af[mt][3],
                            b0, b1);
                }
            }
        }
        __syncthreads();
    }

    // epilogue
#pragma unroll
    for (int mt = 0; mt < 2; mt++) {
#pragma unroll
        for (int nt = 0; nt < 8; nt++) {
            int n = bn + wn * 64 + nt * 8 + tg * 2;
            float bia0 = bias[n], bia1 = bias[n + 1];
#pragma unroll
            for (int half = 0; half < 2; half++) {
                int m = bm + wm * 32 + mt * 16 + g + half * 8;
                float v0 = (acc[mt][nt][half * 2 + 0] + bia0) * scale;
                float v1 = (acc[mt][nt][half * 2 + 1] + bia1) * scale;
                if (MODE == 0) {
                    *reinterpret_cast<float2*>(&C[(size_t)m * EMBED + n]) =
                        make_float2(v0, v1);
                } else {
                    int b_ = m >> 11;
                    int s_ = m & (SEQ - 1);
                    int h_ = n >> 6;
                    int d_ = n & 63;
                    *reinterpret_cast<float2*>(
                        &C[(((size_t)b_ * HEADS + h_) * SEQ + s_) * HEAD_DIM + d_]) =
                        make_float2(v0, v1);
                }
            }
        }
    }
}

// ============================================================
// fp16 tensor-core causal flash attention (fp32 softmax/accum)
// Q pre-scaled by 0.125*log2(e); exp2-domain softmax.
// CTA: 128 rows, 8 warps x 16 rows; key tile 64.
// Ks2  [key 0..63][d2 0..31]  stride 36 (half2 of consecutive d)
// VsT2 [d 0..63][key2 0..31]  stride 36 (half2 of consecutive keys)
// P never touches smem: acc pairs == fp16 A-fragments.
// ============================================================
#define KS2_STR 36
#define VS2_STR 36

__global__ __launch_bounds__(256, 2) void flash_f16(
    const float* __restrict__ Q, const float* __restrict__ K,
    const float* __restrict__ V, float* __restrict__ Out)
{
    __shared__ __align__(16) uint32_t Ks2[64 * KS2_STR];
    __shared__ __align__(16) uint32_t VsT2[64 * VS2_STR];

    const int tid  = threadIdx.x;
    const int lane = tid & 31;
    const int w    = tid >> 5;
    const int g    = lane >> 2;
    const int tg   = lane & 3;

    const int qb = (int)gridDim.x - 1 - (int)blockIdx.x;  // big workloads first
    const int bh = blockIdx.y;
    const int wrow = qb * 128 + w * 16;

    // ---- Q fragments, fp16 (4 k16 steps) ----
    const float* qbase = Q + ((size_t)bh * SEQ + wrow) * HEAD_DIM;
    uint32_t qf[4][4];
#pragma unroll
    for (int kk = 0; kk < 4; kk++) {
        int d0 = kk * 16 + 2 * tg;
        qf[kk][0] = h2pack(qbase[(size_t)g * 64 + d0],       qbase[(size_t)g * 64 + d0 + 1]);
        qf[kk][1] = h2pack(qbase[(size_t)(g + 8) * 64 + d0], qbase[(size_t)(g + 8) * 64 + d0 + 1]);
        qf[kk][2] = h2pack(qbase[(size_t)g * 64 + d0 + 8],   qbase[(size_t)g * 64 + d0 + 9]);
        qf[kk][3] = h2pack(qbase[(size_t)(g + 8) * 64 + d0 + 8], qbase[(size_t)(g + 8) * 64 + d0 + 9]);
    }

    float oacc[8][4];
#pragma unroll
    for (int nt = 0; nt < 8; nt++)
#pragma unroll
        for (int c = 0; c < 4; c++) oacc[nt][c] = 0.f;

    float m0 = -1e30f, m1 = -1e30f, l0 = 0.f, l1 = 0.f;

    const float4* Kg = reinterpret_cast<const float4*>(K + (size_t)bh * SEQ * HEAD_DIM);
    const float4* Vg = reinterpret_cast<const float4*>(V + (size_t)bh * SEQ * HEAD_DIM);

    // V-transpose fill mapping (per thread, constant across tiles)
    const int vkey2 = tid & 31;       // key pair 0..31
    const int vd8   = tid >> 5;       // d block of 8 (0..7)

    const int nbt = 2 * qb + 2;
    const int nfull = 2 * qb;

    for (int kb = 0; kb < nbt; kb++) {
        const int ks = kb * 64;
        __syncthreads();
        // ---- K fill: [key][d2] half2 of consecutive d ----
#pragma unroll
        for (int i = 0; i < 4; i++) {
            int idx = tid + i * 256;       // 0..1023
            int key = idx >> 4;            // 0..63
            int d4  = idx & 15;            // 0..15
            float4 kv = Kg[(size_t)(ks + key) * 16 + d4];
            Ks2[key * KS2_STR + d4 * 2]     = h2pack(kv.x, kv.y);
            Ks2[key * KS2_STR + d4 * 2 + 1] = h2pack(kv.z, kv.w);
        }
        // ---- V fill transposed: [d][key2] half2 of consecutive keys ----
        {
            int k0 = 2 * vkey2, k1 = k0 + 1;
            float4 va = Vg[(size_t)(ks + k0) * 16 + vd8 * 2];
            float4 vb = Vg[(size_t)(ks + k0) * 16 + vd8 * 2 + 1];
            float4 vc = Vg[(size_t)(ks + k1) * 16 + vd8 * 2];
            float4 vd = Vg[(size_t)(ks + k1) * 16 + vd8 * 2 + 1];
            float fa[8] = {va.x, va.y, va.z, va.w, vb.x, vb.y, vb.z, vb.w};
            float fb[8] = {vc.x, vc.y, vc.z, vc.w, vd.x, vd.y, vd.z, vd.w};
#pragma unroll
            for (int j = 0; j < 8; j++)
                VsT2[(vd8 * 8 + j) * VS2_STR + vkey2] = h2pack(fa[j], fb[j]);
        }
        __syncthreads();

        if (ks <= wrow + 15) {   // warp has >=1 valid key in this tile
            // ---- S = Q K^T ----
            float sacc[8][4];
#pragma unroll
            for (int nt = 0; nt < 8; nt++)
#pragma unroll
                for (int c = 0; c < 4; c++) sacc[nt][c] = 0.f;

#pragma unroll
            for (int kk = 0; kk < 4; kk++) {
#pragma unroll
                for (int nt = 0; nt < 8; nt++) {
                    uint32_t b0 = Ks2[(nt * 8 + g) * KS2_STR + kk * 8 + tg];
                    uint32_t b1 = Ks2[(nt * 8 + g) * KS2_STR + kk * 8 + tg + 4];
                    mma_f16(sacc[nt][0], sacc[nt][1], sacc[nt][2], sacc[nt][3],
                            qf[kk][0], qf[kk][1], qf[kk][2], qf[kk][3], b0, b1);
                }
            }

            if (kb >= nfull) {   // diagonal tile: elementwise causal mask
#pragma unroll
                for (int nt = 0; nt < 8; nt++) {
                    int col = ks + nt * 8 + 2 * tg;
                    if (col     > wrow + g)     sacc[nt][0] = -1e30f;
                    if (col + 1 > wrow + g)     sacc[nt][1] = -1e30f;
                    if (col     > wrow + g + 8) sacc[nt][2] = -1e30f;
                    if (col + 1 > wrow + g + 8) sacc[nt][3] = -1e30f;
                }
            }

            // ---- online softmax (exp2 domain) ----
            float rm0 = -1e30f, rm1 = -1e30f;
#pragma unroll
            for (int nt = 0; nt < 8; nt++) {
                rm0 = fmaxf(rm0, fmaxf(sacc[nt][0], sacc[nt][1]));
                rm1 = fmaxf(rm1, fmaxf(sacc[nt][2], sacc[nt][3]));
            }
            rm0 = fmaxf(rm0, __shfl_xor_sync(0xffffffffu, rm0, 1));
            rm0 = fmaxf(rm0, __shfl_xor_sync(0xffffffffu, rm0, 2));
            rm1 = fmaxf(rm1, __shfl_xor_sync(0xffffffffu, rm1, 1));
            rm1 = fmaxf(rm1, __shfl_xor_sync(0xffffffffu, rm1, 2));

            float mn0 = fmaxf(m0, rm0), mn1 = fmaxf(m1, rm1);
            float a0 = exp2a(m0 - mn0), a1 = exp2a(m1 - mn1);
            m0 = mn0; m1 = mn1;

            float ls0 = 0.f, ls1 = 0.f;
#pragma unroll
            for (int nt = 0; nt < 8; nt++) {
                float p0 = exp2a(sacc[nt][0] - mn0);
                float p1 = exp2a(sacc[nt][1] - mn0);
                float p2 = exp2a(sacc[nt][2] - mn1);
                float p3 = exp2a(sacc[nt][3] - mn1);
                sacc[nt][0] = p0; sacc[nt][1] = p1;
                sacc[nt][2] = p2; sacc[nt][3] = p3;
                ls0 += p0 + p1; ls1 += p2 + p3;
            }
            ls0 += __shfl_xor_sync(0xffffffffu, ls0, 1);
            ls0 += __shfl_xor_sync(0xffffffffu, ls0, 2);
            ls1 += __shfl_xor_sync(0xffffffffu, ls1, 1);
            ls1 += __shfl_xor_sync(0xffffffffu, ls1, 2);
            l0 = l0 * a0 + ls0;
            l1 = l1 * a1 + ls1;

            // rescale O
#pragma unroll
            for (int nt = 0; nt < 8; nt++) {
                oacc[nt][0] *= a0; oacc[nt][1] *= a0;
                oacc[nt][2] *= a1; oacc[nt][3] *= a1;
            }

            // ---- O += P V  (P A-fragments come straight from sacc) ----
#pragma unroll
            for (int kk = 0; kk < 4; kk++) {
                uint32_t pa0 = h2pack(sacc[2 * kk][0],     sacc[2 * kk][1]);
                uint32_t pa1 = h2pack(sacc[2 * kk][2],     sacc[2 * kk][3]);
                uint32_t pa2 = h2pack(sacc[2 * kk + 1][0], sacc[2 * kk + 1][1]);
                uint32_t pa3 = h2pack(sacc[2 * kk + 1][2], sacc[2 * kk + 1][3]);
#pragma unroll
                for (int nt = 0; nt < 8; nt++) {
                    uint32_t b0 = VsT2[(nt * 8 + g) * VS2_STR + kk * 8 + tg];
                    uint32_t b1 = VsT2[(nt * 8 + g) * VS2_STR + kk * 8 + tg + 4];
                    mma_f16(oacc[nt][0], oacc[nt][1], oacc[nt][2], oacc[nt][3],
                            pa0, pa1, pa2, pa3, b0, b1);
                }
            }
        }
    }

    // ---- epilogue: divide by l, scatter to [B,S,EMBED] ----
    float inv0 = 1.f / l0, inv1 = 1.f / l1;
    int b_ = bh >> 4, h_ = bh & 15;
    int r0 = wrow + g, r1 = wrow + g + 8;
    float* o0 = Out + ((size_t)b_ * SEQ + r0) * EMBED + h_ * 64;
    float* o1 = Out + ((size_t)b_ * SEQ + r1) * EMBED + h_ * 64;
#pragma unroll
    for (int nt = 0; nt < 8; nt++) {
        *reinterpret_cast<float2*>(&o0[nt * 8 + 2 * tg]) =
            make_float2(oacc[nt][0] * inv0, oacc[nt][1] * inv0);
        *reinterpret_cast<float2*>(&o1[nt * 8 + 2 * tg]) =
            make_float2(oacc[nt][2] * inv1, oacc[nt][3] * inv1);
    }
}

// ---------------- launch ----------------
extern "C" void kernel_launch(void* const* d_in, const int* in_sizes, int n_in,
                              void* d_out, int out_size)
{
    const float* query  = (const float*)d_in[0];
    const float* key_in = (const float*)d_in[1];
    const float* value  = (const float*)d_in[2];
    // d_in[3] = mask (int32 tril) — causal applied analytically
    const float* Wq = (const float*)d_in[4];
    const float* bq = (const float*)d_in[5];
    const float* Wk = (const float*)d_in[6];
    const float* bk = (const float*)d_in[7];
    const float* Wv = (const float*)d_in[8];
    const float* bv = (const float*)d_in[9];
    const float* Wo = (const float*)d_in[10];
    const float* bo = (const float*)d_in[11];
    float* out = (float*)d_out;

    float *gq, *gk, *gv, *ga;
    cudaGetSymbolAddress((void**)&gq, g_Q);
    cudaGetSymbolAddress((void**)&gk, g_K);
    cudaGetSymbolAddress((void**)&gv, g_V);
    cudaGetSymbolAddress((void**)&ga, g_ATT);

    dim3 gp(EMBED / GBN, MTOT / GBM);   // (8, 64)
    // Q scaled by 1/sqrt(64) * log2(e) so softmax uses ex2 directly
    gemm_f16<1><<<gp, 256>>>(query,  Wq, bq, gq, 0.18033688011112042f);
    gemm_f16<1><<<gp, 256>>>(key_in, Wk, bk, gk, 1.0f);
    gemm_f16<1><<<gp, 256>>>(value,  Wv, bv, gv, 1.0f);

    flash_f16<<<dim3(SEQ / 128, BATCH * HEADS), 256>>>(gq, gk, gv, ga);

    gemm_f16<0><<<gp, 256>>>(ga, Wo, bo, out, 1.0f);
}

// round 11
// speedup vs baseline: 12.5437x; 1.1655x over previous
#include <cuda_runtime.h>
#include <cuda_fp16.h>
#include <cstdint>

#define EMBED    1024
#define HEADS    16
#define HEAD_DIM 64
#define BATCH    4
#define SEQ      2048
#define MTOT     (BATCH * SEQ)

// ---------------- scratch (no allocations allowed) ----------------
__device__ __half g_Qh[(size_t)BATCH * HEADS * SEQ * HEAD_DIM];
__device__ __half g_Kh[(size_t)BATCH * HEADS * SEQ * HEAD_DIM];
__device__ __half g_Vh[(size_t)BATCH * HEADS * SEQ * HEAD_DIM];
__device__ float  g_ATT[(size_t)BATCH * SEQ * EMBED];

// ---------------- helpers ----------------
__device__ __forceinline__ uint32_t h2pack(float a, float b) {
    uint32_t r;
    asm("cvt.rn.f16x2.f32 %0, %1, %2;" : "=r"(r) : "f"(b), "f"(a));
    return r;
}

__device__ __forceinline__ float exp2a(float x) {
    float r;
    asm("ex2.approx.f32 %0, %1;" : "=f"(r) : "f"(x));
    return r;
}

__device__ __forceinline__ void mma_f16(
    float& c0, float& c1, float& c2, float& c3,
    uint32_t a0, uint32_t a1, uint32_t a2, uint32_t a3,
    uint32_t b0, uint32_t b1)
{
    asm volatile(
        "mma.sync.aligned.m16n8k16.row.col.f32.f16.f16.f32 "
        "{%0,%1,%2,%3}, {%4,%5,%6,%7}, {%8,%9}, {%0,%1,%2,%3};\n"
        : "+f"(c0), "+f"(c1), "+f"(c2), "+f"(c3)
        : "r"(a0), "r"(a1), "r"(a2), "r"(a3), "r"(b0), "r"(b1));
}

__device__ __forceinline__ uint32_t smem_u32(const void* p) {
    uint32_t a;
    asm("{ .reg .u64 t; cvta.to.shared.u64 t, %1; cvt.u32.u64 %0, t; }"
        : "=r"(a) : "l"(p));
    return a;
}

__device__ __forceinline__ void cp16(uint32_t dst, const void* src) {
    asm volatile("cp.async.cg.shared.global [%0], [%1], 16;" :: "r"(dst), "l"(src));
}
#define CP_COMMIT() asm volatile("cp.async.commit_group;" ::: "memory")
#define CP_WAIT0()  asm volatile("cp.async.wait_group 0;" ::: "memory")

// ============================================================
// fp16 tensor-core GEMM body: C = A[.,1024] @ W[.,1024]^T + bias (x scale)
// CTA 128x128, BK=32, double-buffered smem, one sync per K-iter.
// MODE 0: float out row-major [M,EMBED]. MODE 1: half out scatter [B,H,S,Dh].
// ============================================================
#define GBM 128
#define GBN 128
#define GSTR 20
#define GBUF (GBM * GSTR)          // u32 per buffer
#define KITERS (EMBED / 32)        // 32

template <int MODE>
__device__ __forceinline__ void gemm_body(
    const float* __restrict__ A, const float* __restrict__ W,
    const float* __restrict__ bias, float* __restrict__ Cf,
    __half* __restrict__ Ch, float scale, int bm, int bn,
    uint32_t* As2, uint32_t* Bs2)
{
    const int tid  = threadIdx.x;
    const int lane = tid & 31;
    const int warp = tid >> 5;
    const int wm   = warp >> 1;
    const int wn   = warp & 1;
    const int g    = lane >> 2;
    const int tg   = lane & 3;

    float acc[2][8][4];
#pragma unroll
    for (int i = 0; i < 2; i++)
#pragma unroll
        for (int j = 0; j < 8; j++)
#pragma unroll
            for (int v = 0; v < 4; v++) acc[i][j][v] = 0.f;

    const float4* A4 = reinterpret_cast<const float4*>(A);
    const float4* W4 = reinterpret_cast<const float4*>(W);

    int rowi[4], d4i[4];
#pragma unroll
    for (int i = 0; i < 4; i++) {
        int idx = tid + i * 256;
        rowi[i] = idx >> 3;
        d4i[i]  = idx & 7;
    }

    float4 ra[4], rb[4];
    // load tile 0
#pragma unroll
    for (int i = 0; i < 4; i++) {
        ra[i] = A4[(size_t)(bm + rowi[i]) * 256 + d4i[i]];
        rb[i] = W4[(size_t)(bn + rowi[i]) * 256 + d4i[i]];
    }
    // store tile 0 -> buf 0
#pragma unroll
    for (int i = 0; i < 4; i++) {
        uint2 ua = make_uint2(h2pack(ra[i].x, ra[i].y), h2pack(ra[i].z, ra[i].w));
        *reinterpret_cast<uint2*>(&As2[rowi[i] * GSTR + d4i[i] * 2]) = ua;
        uint2 ub = make_uint2(h2pack(rb[i].x, rb[i].y), h2pack(rb[i].z, rb[i].w));
        *reinterpret_cast<uint2*>(&Bs2[rowi[i] * GSTR + d4i[i] * 2]) = ub;
    }
    // load tile 1
#pragma unroll
    for (int i = 0; i < 4; i++) {
        ra[i] = A4[(size_t)(bm + rowi[i]) * 256 + 8 + d4i[i]];
        rb[i] = W4[(size_t)(bn + rowi[i]) * 256 + 8 + d4i[i]];
    }
    __syncthreads();

    for (int t = 0; t < KITERS; t++) {
        const int s = t & 1;
        const uint32_t* Ab = As2 + s * GBUF;
        const uint32_t* Bb = Bs2 + s * GBUF;

#pragma unroll
        for (int ks = 0; ks < 2; ks++) {
            const int cb = ks * 8;
            uint32_t af[2][4];
#pragma unroll
            for (int mt = 0; mt < 2; mt++) {
                int mrow = wm * 32 + mt * 16 + g;
                af[mt][0] = Ab[mrow * GSTR + cb + tg];
                af[mt][1] = Ab[(mrow + 8) * GSTR + cb + tg];
                af[mt][2] = Ab[mrow * GSTR + cb + tg + 4];
                af[mt][3] = Ab[(mrow + 8) * GSTR + cb + tg + 4];
            }
#pragma unroll
            for (int nt = 0; nt < 8; nt++) {
                int nrow = wn * 64 + nt * 8 + g;
                uint32_t b0 = Bb[nrow * GSTR + cb + tg];
                uint32_t b1 = Bb[nrow * GSTR + cb + tg + 4];
#pragma unroll
                for (int mt = 0; mt < 2; mt++) {
                    mma_f16(acc[mt][nt][0], acc[mt][nt][1],
                            acc[mt][nt][2], acc[mt][nt][3],
                            af[mt][0], af[mt][1], af[mt][2], af[mt][3],
                            b0, b1);
                }
            }
        }

        if (t + 1 < KITERS) {
            uint32_t* Aw = As2 + (s ^ 1) * GBUF;
            uint32_t* Bw = Bs2 + (s ^ 1) * GBUF;
#pragma unroll
            for (int i = 0; i < 4; i++) {
                uint2 ua = make_uint2(h2pack(ra[i].x, ra[i].y), h2pack(ra[i].z, ra[i].w));
                *reinterpret_cast<uint2*>(&Aw[rowi[i] * GSTR + d4i[i] * 2]) = ua;
                uint2 ub = make_uint2(h2pack(rb[i].x, rb[i].y), h2pack(rb[i].z, rb[i].w));
                *reinterpret_cast<uint2*>(&Bw[rowi[i] * GSTR + d4i[i] * 2]) = ub;
            }
            if (t + 2 < KITERS) {
                int kf = (t + 2) * 8;
#pragma unroll
                for (int i = 0; i < 4; i++) {
                    ra[i] = A4[(size_t)(bm + rowi[i]) * 256 + kf + d4i[i]];
                    rb[i] = W4[(size_t)(bn + rowi[i]) * 256 + kf + d4i[i]];
                }
            }
        }
        __syncthreads();
    }

    // epilogue
#pragma unroll
    for (int mt = 0; mt < 2; mt++) {
#pragma unroll
        for (int nt = 0; nt < 8; nt++) {
            int n = bn + wn * 64 + nt * 8 + tg * 2;
            float bia0 = bias[n], bia1 = bias[n + 1];
#pragma unroll
            for (int half = 0; half < 2; half++) {
                int m = bm + wm * 32 + mt * 16 + g + half * 8;
                float v0 = (acc[mt][nt][half * 2 + 0] + bia0) * scale;
                float v1 = (acc[mt][nt][half * 2 + 1] + bia1) * scale;
                if (MODE == 0) {
                    *reinterpret_cast<float2*>(&Cf[(size_t)m * EMBED + n]) =
                        make_float2(v0, v1);
                } else {
                    int b_ = m >> 11;
                    int s_ = m & (SEQ - 1);
                    int h_ = n >> 6;
                    int d_ = n & 63;
                    *reinterpret_cast<uint32_t*>(
                        &Ch[(((size_t)b_ * HEADS + h_) * SEQ + s_) * HEAD_DIM + d_]) =
                        h2pack(v0, v1);
                }
            }
        }
    }
}

__global__ __launch_bounds__(256, 2) void gemm_qkv(
    const float* __restrict__ q, const float* __restrict__ k,
    const float* __restrict__ v,
    const float* __restrict__ Wq, const float* __restrict__ Wk,
    const float* __restrict__ Wv,
    const float* __restrict__ bq, const float* __restrict__ bk,
    const float* __restrict__ bv,
    __half* __restrict__ oq, __half* __restrict__ ok, __half* __restrict__ ov)
{
    __shared__ __align__(16) uint32_t As2[2 * GBUF];
    __shared__ __align__(16) uint32_t Bs2[2 * GBUF];
    const float *A, *W, *bias;
    __half* C;
    float scale = 1.0f;
    if (blockIdx.z == 0) {
        A = q; W = Wq; bias = bq; C = oq;
        scale = 0.18033688011112042f;     // 1/sqrt(64) * log2(e)
    } else if (blockIdx.z == 1) {
        A = k; W = Wk; bias = bk; C = ok;
    } else {
        A = v; W = Wv; bias = bv; C = ov;
    }
    gemm_body<1>(A, W, bias, nullptr, C, scale,
                 blockIdx.y * GBM, blockIdx.x * GBN, As2, Bs2);
}

__global__ __launch_bounds__(256, 2) void gemm_out(
    const float* __restrict__ A, const float* __restrict__ W,
    const float* __restrict__ bias, float* __restrict__ C)
{
    __shared__ __align__(16) uint32_t As2[2 * GBUF];
    __shared__ __align__(16) uint32_t Bs2[2 * GBUF];
    gemm_body<0>(A, W, bias, C, nullptr, 1.0f,
                 blockIdx.y * GBM, blockIdx.x * GBN, As2, Bs2);
}

// ============================================================
// fp16 flash attention, double-buffered tiles, cp.async K fills.
// Q pre-scaled by 0.125*log2(e); exp2-domain softmax.
// CTA 128 rows, 8 warps x 16; key tile 64; 1 sync per tile.
// K smem [key][d2] stride 36 u32 (cp.async raw, 144B rows).
// V smem [d][key2] stride 36 u32 (register-staged transpose).
// ============================================================
#define FSTR 36
#define FBUF (64 * FSTR)       // u32 per buffer

__global__ __launch_bounds__(256, 2) void flash_f16(
    const __half* __restrict__ Q, const __half* __restrict__ K,
    const __half* __restrict__ V, float* __restrict__ Out)
{
    __shared__ __align__(16) uint32_t KS[2 * FBUF];
    __shared__ __align__(16) uint32_t VS[2 * FBUF];

    const int tid  = threadIdx.x;
    const int lane = tid & 31;
    const int w    = tid >> 5;
    const int g    = lane >> 2;
    const int tg   = lane & 3;

    const int qb = (int)gridDim.x - 1 - (int)blockIdx.x;
    const int bh = blockIdx.y;
    const int wrow = qb * 128 + w * 16;

    const uint32_t ksbase = smem_u32(KS);
    const __half* Kg = K + (size_t)bh * SEQ * HEAD_DIM;
    const __half* Vg = V + (size_t)bh * SEQ * HEAD_DIM;

    // ---- Q fragments: direct packed-half2 loads ----
    const __half* qbase = Q + ((size_t)bh * SEQ + wrow) * HEAD_DIM;
    uint32_t qf[4][4];
#pragma unroll
    for (int kk = 0; kk < 4; kk++) {
        int d0 = kk * 16 + 2 * tg;
        qf[kk][0] = *reinterpret_cast<const uint32_t*>(qbase + (size_t)g * 64 + d0);
        qf[kk][1] = *reinterpret_cast<const uint32_t*>(qbase + (size_t)(g + 8) * 64 + d0);
        qf[kk][2] = *reinterpret_cast<const uint32_t*>(qbase + (size_t)g * 64 + d0 + 8);
        qf[kk][3] = *reinterpret_cast<const uint32_t*>(qbase + (size_t)(g + 8) * 64 + d0 + 8);
    }

    float oacc[8][4];
#pragma unroll
    for (int nt = 0; nt < 8; nt++)
#pragma unroll
        for (int c = 0; c < 4; c++) oacc[nt][c] = 0.f;

    float m0 = -1e30f, m1 = -1e30f, l0 = 0.f, l1 = 0.f;

    // fill mappings
    const int kkey = tid >> 3;          // cp.async: key row (with i offset)
    const int kchk = tid & 7;           // 16B chunk in row
    const int vkey2 = tid & 31;         // V: key pair
    const int vd8   = tid >> 5;         // V: d block of 8

    const int nbt = 2 * qb + 2;
    uint4 va, vb;

    // ---- prologue: tile 0 ----
#pragma unroll
    for (int i = 0; i < 2; i++) {
        int key = kkey + i * 32;
        cp16(ksbase + (key * FSTR + kchk * 4) * 4, Kg + (size_t)key * 64 + kchk * 8);
    }
    CP_COMMIT();
    va = *reinterpret_cast<const uint4*>(Vg + (size_t)(2 * vkey2) * 64 + vd8 * 8);
    vb = *reinterpret_cast<const uint4*>(Vg + (size_t)(2 * vkey2 + 1) * 64 + vd8 * 8);
    {
        const uint32_t* au = reinterpret_cast<const uint32_t*>(&va);
        const uint32_t* bu = reinterpret_cast<const uint32_t*>(&vb);
#pragma unroll
        for (int j = 0; j < 8; j++) {
            uint32_t pk = (j & 1) ? __byte_perm(au[j >> 1], bu[j >> 1], 0x7632)
                                  : __byte_perm(au[j >> 1], bu[j >> 1], 0x5410);
            VS[(vd8 * 8 + j) * FSTR + vkey2] = pk;
        }
    }
    if (nbt > 1) {
        va = *reinterpret_cast<const uint4*>(Vg + (size_t)(64 + 2 * vkey2) * 64 + vd8 * 8);
        vb = *reinterpret_cast<const uint4*>(Vg + (size_t)(64 + 2 * vkey2 + 1) * 64 + vd8 * 8);
    }
    CP_WAIT0();
    __syncthreads();

    for (int kb = 0; kb < nbt; kb++) {
        const int s = kb & 1;
        const int ks = kb * 64;

        // stage tile kb+1 into buffer s^1 (safe: last read at kb-1, synced)
        if (kb + 1 < nbt) {
            const int ksn = ks + 64;
#pragma unroll
            for (int i = 0; i < 2; i++) {
                int key = kkey + i * 32;
                cp16(ksbase + ((s ^ 1) * FBUF + key * FSTR + kchk * 4) * 4,
                     Kg + (size_t)(ksn + key) * 64 + kchk * 8);
            }
            CP_COMMIT();
            const uint32_t* au = reinterpret_cast<const uint32_t*>(&va);
            const uint32_t* bu = reinterpret_cast<const uint32_t*>(&vb);
            uint32_t* Vw = VS + (s ^ 1) * FBUF;
#pragma unroll
            for (int j = 0; j < 8; j++) {
                uint32_t pk = (j & 1) ? __byte_perm(au[j >> 1], bu[j >> 1], 0x7632)
                                      : __byte_perm(au[j >> 1], bu[j >> 1], 0x5410);
                Vw[(vd8 * 8 + j) * FSTR + vkey2] = pk;
            }
            if (kb + 2 < nbt) {
                const int ks2 = ks + 128;
                va = *reinterpret_cast<const uint4*>(
                    Vg + (size_t)(ks2 + 2 * vkey2) * 64 + vd8 * 8);
                vb = *reinterpret_cast<const uint4*>(
                    Vg + (size_t)(ks2 + 2 * vkey2 + 1) * 64 + vd8 * 8);
            }
        }

        const uint32_t* Kb = KS + s * FBUF;
        const uint32_t* Vb = VS + s * FBUF;

        if (ks <= wrow + 15) {
            // ---- S = Q K^T ----
            float sacc[8][4];
#pragma unroll
            for (int nt = 0; nt < 8; nt++)
#pragma unroll
                for (int c = 0; c < 4; c++) sacc[nt][c] = 0.f;

#pragma unroll
            for (int kk = 0; kk < 4; kk++) {
#pragma unroll
                for (int nt = 0; nt < 8; nt++) {
                    uint32_t b0 = Kb[(nt * 8 + g) * FSTR + kk * 8 + tg];
                    uint32_t b1 = Kb[(nt * 8 + g) * FSTR + kk * 8 + tg + 4];
                    mma_f16(sacc[nt][0], sacc[nt][1], sacc[nt][2], sacc[nt][3],
                            qf[kk][0], qf[kk][1], qf[kk][2], qf[kk][3], b0, b1);
                }
            }

            if (ks + 64 > wrow) {   // diagonal tile: elementwise causal mask
#pragma unroll
                for (int nt = 0; nt < 8; nt++) {
                    int col = ks + nt * 8 + 2 * tg;
                    if (col     > wrow + g)     sacc[nt][0] = -1e30f;
                    if (col + 1 > wrow + g)     sacc[nt][1] = -1e30f;
                    if (col     > wrow + g + 8) sacc[nt][2] = -1e30f;
                    if (col + 1 > wrow + g + 8) sacc[nt][3] = -1e30f;
                }
            }

            // ---- online softmax (exp2 domain) ----
            float rm0 = -1e30f, rm1 = -1e30f;
#pragma unroll
            for (int nt = 0; nt < 8; nt++) {
                rm0 = fmaxf(rm0, fmaxf(sacc[nt][0], sacc[nt][1]));
                rm1 = fmaxf(rm1, fmaxf(sacc[nt][2], sacc[nt][3]));
            }
            rm0 = fmaxf(rm0, __shfl_xor_sync(0xffffffffu, rm0, 1));
            rm0 = fmaxf(rm0, __shfl_xor_sync(0xffffffffu, rm0, 2));
            rm1 = fmaxf(rm1, __shfl_xor_sync(0xffffffffu, rm1, 1));
            rm1 = fmaxf(rm1, __shfl_xor_sync(0xffffffffu, rm1, 2));

            float mn0 = fmaxf(m0, rm0), mn1 = fmaxf(m1, rm1);
            float a0 = exp2a(m0 - mn0), a1 = exp2a(m1 - mn1);
            m0 = mn0; m1 = mn1;

            float ls0 = 0.f, ls1 = 0.f;
#pragma unroll
            for (int nt = 0; nt < 8; nt++) {
                float p0 = exp2a(sacc[nt][0] - mn0);
                float p1 = exp2a(sacc[nt][1] - mn0);
                float p2 = exp2a(sacc[nt][2] - mn1);
                float p3 = exp2a(sacc[nt][3] - mn1);
                sacc[nt][0] = p0; sacc[nt][1] = p1;
                sacc[nt][2] = p2; sacc[nt][3] = p3;
                ls0 += p0 + p1; ls1 += p2 + p3;
            }
            ls0 += __shfl_xor_sync(0xffffffffu, ls0, 1);
            ls0 += __shfl_xor_sync(0xffffffffu, ls0, 2);
            ls1 += __shfl_xor_sync(0xffffffffu, ls1, 1);
            ls1 += __shfl_xor_sync(0xffffffffu, ls1, 2);
            l0 = l0 * a0 + ls0;
            l1 = l1 * a1 + ls1;

#pragma unroll
            for (int nt = 0; nt < 8; nt++) {
                oacc[nt][0] *= a0; oacc[nt][1] *= a0;
                oacc[nt][2] *= a1; oacc[nt][3] *= a1;
            }

            // ---- O += P V (P fragments direct from registers) ----
#pragma unroll
            for (int kk = 0; kk < 4; kk++) {
                uint32_t pa0 = h2pack(sacc[2 * kk][0],     sacc[2 * kk][1]);
                uint32_t pa1 = h2pack(sacc[2 * kk][2],     sacc[2 * kk][3]);
                uint32_t pa2 = h2pack(sacc[2 * kk + 1][0], sacc[2 * kk + 1][1]);
                uint32_t pa3 = h2pack(sacc[2 * kk + 1][2], sacc[2 * kk + 1][3]);
#pragma unroll
                for (int nt = 0; nt < 8; nt++) {
                    uint32_t b0 = Vb[(nt * 8 + g) * FSTR + kk * 8 + tg];
                    uint32_t b1 = Vb[(nt * 8 + g) * FSTR + kk * 8 + tg + 4];
                    mma_f16(oacc[nt][0], oacc[nt][1], oacc[nt][2], oacc[nt][3],
                            pa0, pa1, pa2, pa3, b0, b1);
                }
            }
        }

        if (kb + 1 < nbt) CP_WAIT0();
        __syncthreads();
    }

    // ---- epilogue: divide by l, scatter to [B,S,EMBED] ----
    float inv0 = 1.f / l0, inv1 = 1.f / l1;
    int b_ = bh >> 4, h_ = bh & 15;
    int r0 = wrow + g, r1 = wrow + g + 8;
    float* o0 = Out + ((size_t)b_ * SEQ + r0) * EMBED + h_ * 64;
    float* o1 = Out + ((size_t)b_ * SEQ + r1) * EMBED + h_ * 64;
#pragma unroll
    for (int nt = 0; nt < 8; nt++) {
        *reinterpret_cast<float2*>(&o0[nt * 8 + 2 * tg]) =
            make_float2(oacc[nt][0] * inv0, oacc[nt][1] * inv0);
        *reinterpret_cast<float2*>(&o1[nt * 8 + 2 * tg]) =
            make_float2(oacc[nt][2] * inv1, oacc[nt][3] * inv1);
    }
}

// ---------------- launch ----------------
extern "C" void kernel_launch(void* const* d_in, const int* in_sizes, int n_in,
                              void* d_out, int out_size)
{
    const float* query  = (const float*)d_in[0];
    const float* key_in = (const float*)d_in[1];
    const float* value  = (const float*)d_in[2];
    // d_in[3] = mask (int32 tril) — causal applied analytically
    const float* Wq = (const float*)d_in[4];
    const float* bq = (const float*)d_in[5];
    const float* Wk = (const float*)d_in[6];
    const float* bk = (const float*)d_in[7];
    const float* Wv = (const float*)d_in[8];
    const float* bv = (const float*)d_in[9];
    const float* Wo = (const float*)d_in[10];
    const float* bo = (const float*)d_in[11];
    float* out = (float*)d_out;

    __half *gq, *gk, *gv;
    float* ga;
    cudaGetSymbolAddress((void**)&gq, g_Qh);
    cudaGetSymbolAddress((void**)&gk, g_Kh);
    cudaGetSymbolAddress((void**)&gv, g_Vh);
    cudaGetSymbolAddress((void**)&ga, g_ATT);

    dim3 gqkv(EMBED / GBN, MTOT / GBM, 3);   // (8, 64, 3)
    gemm_qkv<<<gqkv, 256>>>(query, key_in, value,
                            Wq, Wk, Wv, bq, bk, bv, gq, gk, gv);

    flash_f16<<<dim3(SEQ / 128, BATCH * HEADS), 256>>>(gq, gk, gv, ga);

    gemm_out<<<dim3(EMBED / GBN, MTOT / GBM), 256>>>(ga, Wo, bo, out);
}